// round 2
// baseline (speedup 1.0000x reference)
#include <cuda_runtime.h>
#include <cstdint>

#define D       128
#define NB      6
#define OUTW    (D * NB + D)   // 896
#define MTILE   64
#define THREADS 256
#define SMEM_BYTES ((D * D + MTILE * D) * (int)sizeof(float))  // 96 KB

// Packed f32x2 helpers (Blackwell: 2x FFMA throughput vs scalar 3-reg FFMA)
#define PACK2(d, lo, hi) asm("mov.b64 %0, {%1, %2};" : "=l"(d) : "f"(lo), "f"(hi))
#define UNPACK2(lo, hi, s) asm("mov.b64 {%0, %1}, %2;" : "=f"(lo), "=f"(hi) : "l"(s))
#define FMA2(d, a, b) asm("fma.rn.f32x2 %0, %1, %2, %0;" : "+l"(d) : "l"(a), "l"(b))

// Scratch: sigmoid(W) computed once per launch (device global: no allocs allowed)
__device__ float g_S[D * D];

__global__ void sigmoid_kernel(const float* __restrict__ W) {
    int i = blockIdx.x * blockDim.x + threadIdx.x;
    if (i < D * D) {
        float w = W[i];
        g_S[i] = 1.0f / (1.0f + __expf(-w));
    }
}

__global__ __launch_bounds__(THREADS)
void kan_fused_kernel(const float* __restrict__ x,
                      float* __restrict__ out,
                      int rows)
{
    extern __shared__ float sh[];
    float* Ssh  = sh;            // [128][128] sigmoid(W)
    float* x2sh = sh + D * D;    // [64][128]  x^2 tile

    const int tid = threadIdx.x;
    const int r0  = blockIdx.x * MTILE;

    // ---- load S (already sigmoided) into shared, coalesced float4 ----
    {
        const float4* src = (const float4*)g_S;
        float4*       dst = (float4*)Ssh;
        #pragma unroll
        for (int q = 0; q < (D * D / 4) / THREADS; ++q)   // 16 iters
            dst[tid + q * THREADS] = src[tid + q * THREADS];
    }

    // ---- stage A: load x, compute+store B-spline basis, stage x^2 ----
    // Uniform knots over [-1,1], h = 2/9. Cox-de Boor collapses to the
    // cardinal cubic weights; interval j = floor((xc+1)*4.5), u = frac.
    const float XMAX = 1.0f - 1e-6f;   // knots[-1] - eps, same fp expr as ref
    #pragma unroll
    for (int q = 0; q < 8; ++q) {
        int idx4 = tid + q * THREADS;       // 0..2047 (float4 index in tile)
        int lr   = idx4 >> 5;               // local row 0..63
        int c4   = idx4 & 31;               // float4 col 0..31
        int grow = r0 + lr;
        if (grow < rows) {
            float4 xv = ((const float4*)(x + (size_t)grow * D))[c4];

            // x^2 to shared (conflict-free: warp lanes cover one 512B row)
            float4 x2;
            x2.x = xv.x * xv.x; x2.y = xv.y * xv.y;
            x2.z = xv.z * xv.z; x2.w = xv.w * xv.w;
            ((float4*)(x2sh + lr * D))[c4] = x2;

            // basis for 4 elements -> 24 floats, fully in registers
            float v[4][6];
            #pragma unroll
            for (int e = 0; e < 4; ++e) {
                float xe = (&xv.x)[e];
                float xc = fminf(fmaxf(xe, -1.0f), XMAX);
                float t  = (xc + 1.0f) * 4.5f;
                float jf = floorf(t);
                int   j  = (int)jf;
                float u  = t - jf;
                float u2 = u * u;
                float u3 = u2 * u;
                float om = 1.0f - u;
                float w0 = (1.0f / 6.0f) * om * om * om;          // N_{j-3}
                float w1 = 0.5f * u3 - u2 + (2.0f / 3.0f);        // N_{j-2}
                float w2 = -0.5f * u3 + 0.5f * u2 + 0.5f * u + (1.0f / 6.0f); // N_{j-1}
                float w3 = (1.0f / 6.0f) * u3;                    // N_{j}
                #pragma unroll
                for (int i = 0; i < NB; ++i) {
                    float r = 0.0f;
                    r = (j == i    ) ? w3 : r;
                    r = (j == i + 1) ? w2 : r;
                    r = (j == i + 2) ? w1 : r;
                    r = (j == i + 3) ? w0 : r;
                    v[e][i] = r;
                }
            }
            // 24 floats -> 6 coalesced STG.128 (base offset c4*24 floats = 96B, aligned)
            float4* ob = (float4*)(out + (size_t)grow * OUTW + c4 * 24);
            ob[0] = make_float4(v[0][0], v[0][1], v[0][2], v[0][3]);
            ob[1] = make_float4(v[0][4], v[0][5], v[1][0], v[1][1]);
            ob[2] = make_float4(v[1][2], v[1][3], v[1][4], v[1][5]);
            ob[3] = make_float4(v[2][0], v[2][1], v[2][2], v[2][3]);
            ob[4] = make_float4(v[2][4], v[2][5], v[3][0], v[3][1]);
            ob[5] = make_float4(v[3][2], v[3][3], v[3][4], v[3][5]);
        }
    }
    __syncthreads();

    // ---- stage B: 64x128x128 GEMM, TM=8 x TN=4 register tile, f32x2 FMAs ----
    const int tr = tid >> 5;   // 0..7  (M thread row)
    const int tc = tid & 31;   // 0..31 (N thread col, 4 floats each)

    unsigned long long acc[8][2];
    #pragma unroll
    for (int m = 0; m < 8; ++m) { acc[m][0] = 0ull; acc[m][1] = 0ull; }

    const float* xbase = x2sh + (tr * 8) * D;
    const float* sbase = Ssh + tc * 4;

    #pragma unroll 2
    for (int k = 0; k < D; k += 4) {
        unsigned long long sp[4][2];
        #pragma unroll
        for (int kk = 0; kk < 4; ++kk) {
            // warp lanes read 512B contiguous -> conflict-free LDS.128
            float4 s = *(const float4*)(sbase + (k + kk) * D);
            PACK2(sp[kk][0], s.x, s.y);
            PACK2(sp[kk][1], s.z, s.w);
        }
        #pragma unroll
        for (int m = 0; m < 8; ++m) {
            float4 xq = *(const float4*)(xbase + m * D + k);  // broadcast
            unsigned long long xx;
            PACK2(xx, xq.x, xq.x);
            FMA2(acc[m][0], xx, sp[0][0]); FMA2(acc[m][1], xx, sp[0][1]);
            PACK2(xx, xq.y, xq.y);
            FMA2(acc[m][0], xx, sp[1][0]); FMA2(acc[m][1], xx, sp[1][1]);
            PACK2(xx, xq.z, xq.z);
            FMA2(acc[m][0], xx, sp[2][0]); FMA2(acc[m][1], xx, sp[2][1]);
            PACK2(xx, xq.w, xq.w);
            FMA2(acc[m][0], xx, sp[3][0]); FMA2(acc[m][1], xx, sp[3][1]);
        }
    }

    // ---- stage C: interaction writes, coalesced float4 ----
    #pragma unroll
    for (int m = 0; m < 8; ++m) {
        int grow = r0 + tr * 8 + m;
        if (grow < rows) {
            float a, b, c, d2;
            UNPACK2(a, b, acc[m][0]);
            UNPACK2(c, d2, acc[m][1]);
            *(float4*)(out + (size_t)grow * OUTW + NB * D + tc * 4) =
                make_float4(a, b, c, d2);
        }
    }
}

extern "C" void kernel_launch(void* const* d_in, const int* in_sizes, int n_in,
                              void* d_out, int out_size) {
    const float* x = (const float*)d_in[0];
    const float* W = (const float*)d_in[1];
    float* out = (float*)d_out;
    int rows = in_sizes[0] / D;

    cudaFuncSetAttribute(kan_fused_kernel,
                         cudaFuncAttributeMaxDynamicSharedMemorySize, SMEM_BYTES);

    sigmoid_kernel<<<(D * D + THREADS - 1) / THREADS, THREADS>>>(W);

    int grid = (rows + MTILE - 1) / MTILE;
    kan_fused_kernel<<<grid, THREADS, SMEM_BYTES>>>(x, out, rows);
}